// round 10
// baseline (speedup 1.0000x reference)
#include <cuda_runtime.h>
#include <cstdint>

// MultiScaleProcessor: input [64,256,256,3] f32 -> output [64,4,256,256,3] f32
// scales = {32,64,128,256}; bilinear (linspace endpoints), zero-pad to 256.
//
// Pipelined TMA bulk stores: each block streams a 32-row band as 8 chunks of
// 4 rows. Zero chunks store from a never-overwritten zeroed buffer (no wait);
// copy/compute chunks double-buffer with wait_group.read for smem reuse.

#define HH 256
#define WW 256
#define NB 64
#define ROWF (WW * 3)            // 768 floats per row
#define NT 256
#define CH 4                     // rows per chunk (pads 112,96,64 are %4==0)
#define BAND 32                  // rows per block
#define NCH (BAND / CH)          // 8 chunks per block
#define CBYTES (CH * ROWF * 4)   // 12288 bytes per chunk
#define CV (CH * ROWF / 4)       // 768 float4 per chunk
#define VPT (CV / NT)            // 3 float4 per thread
#define PPT (CH * WW / NT)       // 4 pixels per thread

__device__ __forceinline__ uint32_t smem_u32(const void* p) {
    uint32_t a;
    asm("{ .reg .u64 t; cvta.to.shared.u64 t, %1; cvt.u32.u64 %0, t; }"
        : "=r"(a) : "l"(p));
    return a;
}

__device__ __forceinline__ void fence_async() {
    asm volatile("fence.proxy.async.shared::cta;" ::: "memory");
}

__device__ __forceinline__ void bulk_store(void* gdst, uint32_t ssrc) {
    asm volatile(
        "cp.async.bulk.global.shared::cta.bulk_group [%0], [%1], %2;"
        :: "l"(gdst), "r"(ssrc), "n"(CBYTES) : "memory");
    asm volatile("cp.async.bulk.commit_group;" ::: "memory");
}

__device__ __forceinline__ void wait_read_1() {
    asm volatile("cp.async.bulk.wait_group.read 1;" ::: "memory");
}

__device__ __forceinline__ void wait_all() {
    asm volatile("cp.async.bulk.wait_group 0;" ::: "memory");
}

__global__ __launch_bounds__(NT) void msp_kernel(const float* __restrict__ in,
                                                 float* __restrict__ out) {
    __shared__ __align__(16) float zbuf[CH * ROWF];      // 12 KB, zeros
    __shared__ __align__(16) float dbuf[2][CH * ROWF];   // 2 x 12 KB staging

    const int band = blockIdx.x;         // 0..7 (32-row band)
    const int sc   = blockIdx.y;         // scale index
    const int b    = blockIdx.z;         // batch
    const int s    = 32 << sc;
    const int p    = (256 - s) >> 1;
    const int tid  = threadIdx.x;

    const uint32_t zaddr = smem_u32(zbuf);
    const float4 z4 = make_float4(0.f, 0.f, 0.f, 0.f);
#pragma unroll
    for (int j = 0; j < VPT; j++)
        ((float4*)zbuf)[tid + j * NT] = z4;
    __syncthreads();
    if (tid == 0) fence_async();   // covers zbuf for all later bulk stores
    __syncthreads();

    float* const obase = out + (((size_t)b * 4 + sc) * HH) * ROWF;
    const float* __restrict__ ibase = in + (size_t)b * (HH * ROWF);
    const float inv = 255.0f / (float)(s - 1);

    int d = 0;  // data-chunk counter (copy/compute chunks only)

    for (int c = 0; c < NCH; c++) {
        const int yc = band * BAND + c * CH;
        float* const gdst = obase + (size_t)yc * ROWF;

        const bool is_zero = (s != 256) && (yc + CH <= p || yc >= p + s);
        if (is_zero) {
            // zero chunk: store straight from zbuf, no wait needed
            if (tid == 0) bulk_store(gdst, zaddr);
            continue;
        }

        float* const buf = dbuf[d & 1];
        // before refilling a previously-used buffer, drain its smem read
        if (d >= 2 && tid == 0) wait_read_1();
        __syncthreads();

        if (s == 256) {
            // copy chunk: LDG.128 -> STS.128
            const float4* __restrict__ i4 =
                (const float4*)(ibase + (size_t)yc * ROWF);
            float4* const b4 = (float4*)buf;
#pragma unroll
            for (int j = 0; j < VPT; j++)
                b4[tid + j * NT] = __ldg(&i4[tid + j * NT]);
        } else {
            // compute chunk: bilinear into staging
#pragma unroll
            for (int j = 0; j < PPT; j++) {
                const int pi = tid + j * NT;   // 0..1023
                const int r  = pi >> 8;        // local row 0..3
                const int x  = pi & 255;       // column 0..255
                float* dst = &buf[r * ROWF + 3 * x];
                if (x < p || x >= p + s) {
                    dst[0] = 0.f; dst[1] = 0.f; dst[2] = 0.f;
                } else {
                    const float fy = (float)(yc + r - p) * inv;
                    const int   y0 = (int)fy;        // fy>=0: trunc==floor
                    const int   y1 = min(y0 + 1, HH - 1);
                    const float wy = fy - (float)y0;

                    const float fx = (float)(x - p) * inv;
                    const int   x0 = (int)fx;
                    const int   x1 = min(x0 + 1, WW - 1);
                    const float wx = fx - (float)x0;

                    const float* __restrict__ r0 = ibase + (size_t)y0 * ROWF;
                    const float* __restrict__ r1 = ibase + (size_t)y1 * ROWF;
                    const float wx0 = 1.f - wx;
                    const float wy0 = 1.f - wy;
#pragma unroll
                    for (int ch = 0; ch < 3; ch++) {
                        const float t  = __ldg(r0 + 3 * x0 + ch) * wx0 +
                                         __ldg(r0 + 3 * x1 + ch) * wx;
                        const float bt = __ldg(r1 + 3 * x0 + ch) * wx0 +
                                         __ldg(r1 + 3 * x1 + ch) * wx;
                        dst[ch] = t * wy0 + bt * wy;
                    }
                }
            }
        }
        __syncthreads();
        if (tid == 0) {
            fence_async();
            bulk_store(gdst, smem_u32(buf));
        }
        d++;
    }

    if (tid == 0) wait_all();  // all stores durable before block exit
}

extern "C" void kernel_launch(void* const* d_in, const int* in_sizes, int n_in,
                              void* d_out, int out_size) {
    const float* in  = (const float*)d_in[0];
    float*       out = (float*)d_out;
    (void)in_sizes; (void)n_in; (void)out_size;

    dim3 grid(HH / BAND, 4, NB);  // 8 x 4 x 64 = 2048 blocks
    msp_kernel<<<grid, NT>>>(in, out);
}

// round 12
// speedup vs baseline: 1.2609x; 1.2609x over previous
#include <cuda_runtime.h>
#include <cstdint>

// MultiScaleProcessor: input [64,256,256,3] f32 -> output [64,4,256,256,3] f32
// scales = {32,64,128,256}; bilinear (linspace endpoints), zero-pad to 256.
//
// TMA bulk-store variant (R8 structure: 8192 independent blocks, one 24KB
// burst each). Block exit waits only for the SMEM *read* side of the bulk
// store (cp.async.bulk.wait_group.read 0, the CUTLASS tma_store_wait pattern)
// instead of full write completion — the in-flight global writes are made
// durable by the kernel-boundary fence.

#define HH 256
#define WW 256
#define NB 64
#define ROWF (WW * 3)            // 768 floats per row
#define CHUNK 8                  // rows per block; pads (112,96,64) %8==0
#define NT 256
#define CBYTES (CHUNK * ROWF * 4)    // 24576 bytes per chunk
#define CROWV (CHUNK * ROWF / 4)     // 1536 float4 per chunk
#define VPT (CROWV / NT)             // 6 float4 per thread
#define PPT (CHUNK * WW / NT)        // 8 pixels per thread

__device__ __forceinline__ uint32_t smem_u32(const void* p) {
    uint32_t a;
    asm("{ .reg .u64 t; cvta.to.shared.u64 t, %1; cvt.u32.u64 %0, t; }"
        : "=r"(a) : "l"(p));
    return a;
}

__device__ __forceinline__ void bulk_store_flush(void* gdst, uint32_t ssrc) {
    asm volatile("fence.proxy.async.shared::cta;" ::: "memory");
    asm volatile(
        "cp.async.bulk.global.shared::cta.bulk_group [%0], [%1], %2;"
        :: "l"(gdst), "r"(ssrc), "n"(CBYTES) : "memory");
    asm volatile("cp.async.bulk.commit_group;" ::: "memory");
    // drain only the SMEM-read side; global writes complete asynchronously
    asm volatile("cp.async.bulk.wait_group.read 0;" ::: "memory");
}

__global__ __launch_bounds__(NT) void msp_kernel(const float* __restrict__ in,
                                                 float* __restrict__ out) {
    __shared__ __align__(16) float rows[CHUNK * ROWF];  // 24 KB staging

    const int yc  = blockIdx.x * CHUNK;  // first output row of this chunk
    const int sc  = blockIdx.y;          // scale index
    const int b   = blockIdx.z;          // batch
    const int s   = 32 << sc;
    const int p   = (256 - s) >> 1;
    const int tid = threadIdx.x;

    float* const gdst = out + ((((size_t)b * 4 + sc) * HH + yc) * ROWF);
    float4* const s4  = (float4*)rows;

    if (s == 256) {
        // native: LDG.128 -> STS.128 stage
        const float4* __restrict__ ichunk =
            (const float4*)(in + ((size_t)b * HH + yc) * ROWF);
#pragma unroll
        for (int j = 0; j < VPT; j++)
            s4[tid + j * NT] = __ldg(&ichunk[tid + j * NT]);
    } else if (yc + CHUNK <= p || yc >= p + s) {
        // fully padded chunk: zero the staging buffer
        const float4 z = make_float4(0.f, 0.f, 0.f, 0.f);
#pragma unroll
        for (int j = 0; j < VPT; j++)
            s4[tid + j * NT] = z;
    } else {
        // compute chunk: bilinear into shared
        const float inv = 255.0f / (float)(s - 1);
        const float* __restrict__ base = in + (size_t)b * (HH * ROWF);
#pragma unroll
        for (int j = 0; j < PPT; j++) {
            const int pi = tid + j * NT;   // 0..2047
            const int r  = pi >> 8;        // local row 0..7
            const int x  = pi & 255;       // column 0..255
            float* dst = &rows[r * ROWF + 3 * x];
            if (x < p || x >= p + s) {
                dst[0] = 0.f; dst[1] = 0.f; dst[2] = 0.f;
            } else {
                const int   y  = yc + r - p;
                const float fy = (float)y * inv;
                const int   y0 = (int)fy;          // fy >= 0: trunc == floor
                const int   y1 = min(y0 + 1, HH - 1);
                const float wy = fy - (float)y0;

                const float fx = (float)(x - p) * inv;
                const int   x0 = (int)fx;
                const int   x1 = min(x0 + 1, WW - 1);
                const float wx = fx - (float)x0;

                const float* __restrict__ r0 = base + (size_t)y0 * ROWF;
                const float* __restrict__ r1 = base + (size_t)y1 * ROWF;
                const float wx0 = 1.f - wx;
                const float wy0 = 1.f - wy;
#pragma unroll
                for (int c = 0; c < 3; c++) {
                    const float t  = __ldg(r0 + 3 * x0 + c) * wx0 +
                                     __ldg(r0 + 3 * x1 + c) * wx;
                    const float bt = __ldg(r1 + 3 * x0 + c) * wx0 +
                                     __ldg(r1 + 3 * x1 + c) * wx;
                    dst[c] = t * wy0 + bt * wy;
                }
            }
        }
    }

    __syncthreads();
    if (tid == 0)
        bulk_store_flush(gdst, smem_u32(rows));
}

extern "C" void kernel_launch(void* const* d_in, const int* in_sizes, int n_in,
                              void* d_out, int out_size) {
    const float* in  = (const float*)d_in[0];
    float*       out = (float*)d_out;
    (void)in_sizes; (void)n_in; (void)out_size;

    dim3 grid(HH / CHUNK, 4, NB);  // 32 x 4 x 64 = 8192 blocks
    msp_kernel<<<grid, NT>>>(in, out);
}